// round 4
// baseline (speedup 1.0000x reference)
#include <cuda_runtime.h>
#include <cuda_fp16.h>
#include <cstdint>

#define D_DIM   256
#define K_DIM   512
#define TILE_M  128
#define NTILES  512
#define THRESH  0.25f

// ---------------- device globals (no runtime allocs) ------------------------
__device__ __align__(16) unsigned short g_cbF[K_DIM * D_DIM];  // fp16 codebook
__device__ float g_esq[K_DIM];
__device__ float g_partials[NTILES];
__device__ int   g_mask_kind;   // 0=int32, 1=uint8, 2=float32

// ---------------- smem layout (dynamic) -------------------------------------
#define OFF_A     0           // z fp16: 128 rows x 512B (swizzled)
#define OFF_B     65536       // 2 bufs x 16KB
#define OFF_ESQ   98304       // 512 f
#define OFF_V1    100352      // 128 f
#define OFF_V2    100864
#define OFF_I1    101376      // 128 i
#define OFF_ZSQ   101888      // 128 f
#define OFF_MV    102400      // 128 f
#define OFF_NFL   102912
#define OFF_FLIST 102928      // 128 i
#define OFF_RV    103440      // 256 f
#define OFF_RI    104464      // 256 i
#define OFF_ZROW  105488      // 256 f
#define SMEM_TOTAL 106752

// ---------------- helpers ---------------------------------------------------
static __device__ __forceinline__ uint32_t smem_u32(const void* p) {
    uint32_t a;
    asm("{ .reg .u64 t; cvta.to.shared.u64 t, %1; cvt.u32.u64 %0, t; }" : "=r"(a) : "l"(p));
    return a;
}
#define LDSM_X4(r0,r1,r2,r3,addr) \
    asm volatile("ldmatrix.sync.aligned.m8n8.x4.shared.b16 {%0,%1,%2,%3}, [%4];" \
        : "=r"(r0),"=r"(r1),"=r"(r2),"=r"(r3) : "r"(addr))
#define MMA_F16(dd, a0,a1,a2,a3, b0,b1) \
    asm volatile("mma.sync.aligned.m16n8k16.row.col.f32.f16.f16.f32 " \
        "{%0,%1,%2,%3}, {%4,%5,%6,%7}, {%8,%9}, {%0,%1,%2,%3};" \
        : "+f"((dd)[0]),"+f"((dd)[1]),"+f"((dd)[2]),"+f"((dd)[3]) \
        : "r"(a0),"r"(a1),"r"(a2),"r"(a3),"r"(b0),"r"(b1))
#define CP_ASYNC16(dst, src) \
    asm volatile("cp.async.cg.shared.global [%0], [%1], 16;" :: "r"(dst), "l"(src) : "memory")
#define CP_COMMIT() asm volatile("cp.async.commit_group;" ::: "memory")
#define CP_WAIT1()  asm volatile("cp.async.wait_group 1;" ::: "memory")
#define CP_WAIT0()  asm volatile("cp.async.wait_group 0;" ::: "memory")

// ---------------- mask dtype detect -----------------------------------------
__global__ void mask_kind_kernel(const void* __restrict__ mask, int mask_words) {
    __shared__ int s_int_ok, s_float_ok;
    int tid = threadIdx.x;
    if (tid == 0) { s_int_ok = 1; s_float_ok = 1; }
    __syncthreads();
    const unsigned int* mw = (const unsigned int*)mask;
    int iok = 1, fok = 1;
    for (int j = 0; j < 4; j++) {
        int w = tid * 4 + j;
        if (w < mask_words) {
            unsigned int v = mw[w];
            if (v > 1u) iok = 0;
            if (v != 0u && v != 0x3F800000u) fok = 0;
        }
    }
    if (!iok) atomicAnd(&s_int_ok, 0);
    if (!fok) atomicAnd(&s_float_ok, 0);
    __syncthreads();
    if (tid == 0) g_mask_kind = s_int_ok ? 0 : (s_float_ok ? 2 : 1);
}

// ---------------- codebook -> fp16 + ||e||^2 (one warp per code) ------------
__global__ void convert_cb_kernel(const float* __restrict__ cb) {
    int warp = (blockIdx.x * blockDim.x + threadIdx.x) >> 5;   // 0..511
    int lane = threadIdx.x & 31;
    const float4* row = (const float4*)(cb + (size_t)warp * D_DIM);
    float4 v0 = row[lane * 2], v1 = row[lane * 2 + 1];
    float vs[8] = { v0.x, v0.y, v0.z, v0.w, v1.x, v1.y, v1.z, v1.w };
    unsigned short hs[8];
    float zs = 0.f;
    #pragma unroll
    for (int e = 0; e < 8; e++) {
        __half h = __float2half_rn(vs[e]);
        hs[e] = *reinterpret_cast<unsigned short*>(&h);
        zs += vs[e] * vs[e];
    }
    uint4 P;
    P.x = (uint32_t)hs[0] | ((uint32_t)hs[1] << 16);
    P.y = (uint32_t)hs[2] | ((uint32_t)hs[3] << 16);
    P.z = (uint32_t)hs[4] | ((uint32_t)hs[5] << 16);
    P.w = (uint32_t)hs[6] | ((uint32_t)hs[7] << 16);
    *(uint4*)(g_cbF + (size_t)warp * D_DIM + lane * 8) = P;
    #pragma unroll
    for (int m = 16; m >= 1; m >>= 1) zs += __shfl_xor_sync(0xFFFFFFFFu, zs, m);
    if (lane == 0) g_esq[warp] = zs;
}

// ---------------- B chunk prefetch (cp.async, swizzled dst) -----------------
static __device__ __forceinline__ void prefetch_B(char* smem, int buf, int nc, int kc, int tid) {
    uint32_t dst_base = smem_u32(smem + OFF_B + buf * 16384);
    #pragma unroll
    for (int j = 0; j < 4; j++) {
        int id = tid + 256 * j;        // 1024 granules: [n 128][g 8]
        int n  = id >> 3;
        int g  = id & 7;
        const unsigned char* src = (const unsigned char*)g_cbF
            + (size_t)(nc * 128 + n) * 512 + kc * 128 + g * 16;
        uint32_t dst = dst_base + n * 128 + ((g ^ (n & 7)) << 4);
        CP_ASYNC16(dst, src);
    }
    CP_COMMIT();
}

// ---------------- main fused kernel -----------------------------------------
__global__ __launch_bounds__(256, 2)
void vq_mma_kernel(const float* __restrict__ z,
                   const void* __restrict__ mask,
                   const float* __restrict__ cb,
                   float* __restrict__ out,
                   int T, int write_idx, int write_loss) {
    extern __shared__ __align__(1024) char smem[];
    const uint32_t sb = smem_u32(smem);
    const int tid = threadIdx.x, w = tid >> 5, lane = tid & 31;
    const long long tbase = (long long)blockIdx.x * TILE_M;

    float* s_esq = (float*)(smem + OFF_ESQ);
    float* s_v1  = (float*)(smem + OFF_V1);
    float* s_v2  = (float*)(smem + OFF_V2);
    int*   s_i1  = (int*)  (smem + OFF_I1);
    float* s_zsq = (float*)(smem + OFF_ZSQ);
    float* s_mv  = (float*)(smem + OFF_MV);
    int*   s_nfl = (int*)  (smem + OFF_NFL);
    int*   s_fls = (int*)  (smem + OFF_FLIST);
    float* s_rv  = (float*)(smem + OFF_RV);
    int*   s_ri  = (int*)  (smem + OFF_RI);
    float* s_zrow= (float*)(smem + OFF_ZROW);

    if (tid == 0) *s_nfl = 0;

    // kick first B chunk while we convert A
    prefetch_B(smem, 0, 0, 0, tid);

    // stage esq
    s_esq[tid] = g_esq[tid];
    s_esq[256 + tid] = g_esq[256 + tid];

    // ---- convert z tile -> swizzled fp16 smem; accumulate z_sq ----
    {
        const int r = tid >> 1, h = tid & 1;
        const float4* zr = (const float4*)(z + (tbase + r) * D_DIM);
        float zs = 0.f;
        #pragma unroll 4
        for (int j = 0; j < 16; j++) {
            int k0 = h * 128 + j * 8;
            float4 q0 = zr[k0 / 4], q1 = zr[k0 / 4 + 1];
            float vs[8] = { q0.x, q0.y, q0.z, q0.w, q1.x, q1.y, q1.z, q1.w };
            unsigned short hs[8];
            #pragma unroll
            for (int e = 0; e < 8; e++) {
                __half hh = __float2half_rn(vs[e]);
                hs[e] = *reinterpret_cast<unsigned short*>(&hh);
                zs += vs[e] * vs[e];
            }
            uint4 H;
            H.x = (uint32_t)hs[0] | ((uint32_t)hs[1] << 16);
            H.y = (uint32_t)hs[2] | ((uint32_t)hs[3] << 16);
            H.z = (uint32_t)hs[4] | ((uint32_t)hs[5] << 16);
            H.w = (uint32_t)hs[6] | ((uint32_t)hs[7] << 16);
            int g  = h * 16 + j;
            int gp = g ^ (r & 7);
            *(uint4*)(smem + OFF_A + r * 512 + gp * 16) = H;
        }
        s_rv[tid] = zs;
    }
    __syncthreads();
    if (tid < TILE_M) s_zsq[tid] = s_rv[2 * tid] + s_rv[2 * tid + 1];

    // ---- GEMM + in-register argmin ----
    float vA1 = 3.0e38f, vA2 = 3.0e38f, vB1 = 3.0e38f, vB2 = 3.0e38f;
    int iA1 = 0, iB1 = 0;
    const int rA = w * 16 + (lane >> 2);                 // lane's output row (c0/c1)
    const int arow = w * 16 + (lane & 15);               // ldmatrix A row
    const uint32_t aBase = sb + OFF_A + arow * 512;
    const int aXor = arow & 7, aQ = lane >> 4;
    const int bn = (lane & 7) + ((lane >= 16) ? 8 : 0);  // ldmatrix B row (within n16)
    const int bQ = (lane >> 3) & 1;

    for (int nc = 0; nc < 4; nc++) {
        float d[16][4];
        #pragma unroll
        for (int t = 0; t < 16; t++)
            #pragma unroll
            for (int q = 0; q < 4; q++) d[t][q] = 0.f;

        for (int kc = 0; kc < 4; kc++) {
            int ci = nc * 4 + kc;
            if (ci < 15) {
                int cn = ci + 1;
                prefetch_B(smem, cn & 1, cn >> 2, cn & 3, tid);
                CP_WAIT1();
            } else {
                CP_WAIT0();
            }
            __syncthreads();
            const uint32_t bBuf = sb + OFF_B + (ci & 1) * 16384;

            for (int ks = 0; ks < 4; ks++) {
                int gA = ((kc * 8 + ks * 2 + aQ) ^ aXor) << 4;
                uint32_t a0, a1, a2, a3;
                LDSM_X4(a0, a1, a2, a3, aBase + gA);
                #pragma unroll
                for (int np = 0; np < 8; np++) {
                    int n = np * 16 + bn;
                    uint32_t baddr = bBuf + n * 128 + (((ks * 2 + bQ) ^ (n & 7)) << 4);
                    uint32_t b0, b1, b2, b3;
                    LDSM_X4(b0, b1, b2, b3, baddr);
                    MMA_F16(d[2*np],   a0, a1, a2, a3, b0, b1);
                    MMA_F16(d[2*np+1], a0, a1, a2, a3, b2, b3);
                }
            }
            __syncthreads();
        }

        // fold this n-chunk into running argmin (ascending k => lowest-index ties)
        #pragma unroll
        for (int t = 0; t < 16; t++) {
            int c0 = nc * 128 + t * 8 + 2 * (lane & 3);
            float e0 = s_esq[c0], e1 = s_esq[c0 + 1];
            float s0 = fmaf(-2.f, d[t][0], e0);
            float s1 = fmaf(-2.f, d[t][1], e1);
            float s2 = fmaf(-2.f, d[t][2], e0);
            float s3 = fmaf(-2.f, d[t][3], e1);
            if (s0 < vA1) { vA2 = vA1; vA1 = s0; iA1 = c0; }     else if (s0 < vA2) vA2 = s0;
            if (s1 < vA1) { vA2 = vA1; vA1 = s1; iA1 = c0 + 1; } else if (s1 < vA2) vA2 = s1;
            if (s2 < vB1) { vB2 = vB1; vB1 = s2; iB1 = c0; }     else if (s2 < vB2) vB2 = s2;
            if (s3 < vB1) { vB2 = vB1; vB1 = s3; iB1 = c0 + 1; } else if (s3 < vB2) vB2 = s3;
        }
    }

    // quad reduce (lanes sharing an output row)
    #pragma unroll
    for (int m = 1; m <= 2; m <<= 1) {
        float o1 = __shfl_xor_sync(0xFFFFFFFFu, vA1, m);
        int   oi = __shfl_xor_sync(0xFFFFFFFFu, iA1, m);
        float o2 = __shfl_xor_sync(0xFFFFFFFFu, vA2, m);
        float n2 = fminf(fmaxf(vA1, o1), fminf(vA2, o2));
        if (o1 < vA1 || (o1 == vA1 && oi < iA1)) { vA1 = o1; iA1 = oi; }
        vA2 = n2;
        float p1 = __shfl_xor_sync(0xFFFFFFFFu, vB1, m);
        int   pi = __shfl_xor_sync(0xFFFFFFFFu, iB1, m);
        float p2 = __shfl_xor_sync(0xFFFFFFFFu, vB2, m);
        float q2 = fminf(fmaxf(vB1, p1), fminf(vB2, p2));
        if (p1 < vB1 || (p1 == vB1 && pi < iB1)) { vB1 = p1; iB1 = pi; }
        vB2 = q2;
    }
    if ((lane & 3) == 0) {
        s_v1[rA] = vA1; s_v2[rA] = vA2; s_i1[rA] = iA1;
        s_v1[rA + 8] = vB1; s_v2[rA + 8] = vB2; s_i1[rA + 8] = iB1;
    }
    __syncthreads();
    if (tid < TILE_M) {
        if (s_v2[tid] - s_v1[tid] < THRESH) {
            int p = atomicAdd(s_nfl, 1);
            if (p < 128) s_fls[p] = tid;
        }
    }
    __syncthreads();

    // ---- exact fp32 fallback for ambiguous tokens (rare) ----
    int nf = *s_nfl; if (nf > 128) nf = 128;
    for (int f = 0; f < nf; f++) {
        const int t = s_fls[f];
        s_zrow[tid] = z[(tbase + t) * D_DIM + tid];
        __syncthreads();
        float best = 3.0e38f; int bi = 0;
        #pragma unroll 1
        for (int rep = 0; rep < 2; rep++) {
            int k = tid + rep * 256;
            const float4* crow = (const float4*)(cb + (size_t)k * D_DIM);
            const float4* zr4 = (const float4*)s_zrow;
            float acc = 0.f;
            #pragma unroll 8
            for (int q = 0; q < 64; q++) {
                float4 a = zr4[q]; float4 b = crow[q];
                acc += a.x * b.x + a.y * b.y + a.z * b.z + a.w * b.w;
            }
            float sc = s_esq[k] - 2.0f * acc;
            if (sc < best) { best = sc; bi = k; }
        }
        s_rv[tid] = best; s_ri[tid] = bi;
        __syncthreads();
        for (int st = 128; st > 0; st >>= 1) {
            if (tid < st) {
                float ov = s_rv[tid + st]; int oi2 = s_ri[tid + st];
                if (ov < s_rv[tid] || (ov == s_rv[tid] && oi2 < s_ri[tid])) {
                    s_rv[tid] = ov; s_ri[tid] = oi2;
                }
            }
            __syncthreads();
        }
        if (tid == 0) { s_i1[t] = s_ri[0]; s_v1[t] = s_rv[0]; }
        __syncthreads();
    }

    // ---- epilogue: mask, indices, quantized, loss ----
    const int mkind = g_mask_kind;
    if (tid < TILE_M) {
        long long gt = tbase + tid;
        float mval;
        if (mkind == 0)      mval = ((const int*)mask)[gt] ? 1.f : 0.f;
        else if (mkind == 1) mval = ((const unsigned char*)mask)[gt] ? 1.f : 0.f;
        else                 mval = ((const float*)mask)[gt];
        s_mv[tid] = mval;
        if (write_idx)
            out[(long long)T * D_DIM + gt] = (mval != 0.f) ? (float)s_i1[tid] : -1.0f;
    }
    __syncthreads();
    {
        const int dcol = tid;
        #pragma unroll 4
        for (int t = 0; t < TILE_M; t++) {
            int k = s_i1[t];
            out[(tbase + t) * D_DIM + dcol] = cb[(size_t)k * D_DIM + dcol] * s_mv[t];
        }
    }
    if (write_loss) {
        if (tid < TILE_M) s_rv[tid] = s_zsq[tid] + s_v1[tid];   // ||z-e||^2
        __syncthreads();
        for (int st = 64; st > 0; st >>= 1) {
            if (tid < st) s_rv[tid] += s_rv[tid + st];
            __syncthreads();
        }
        if (tid == 0) g_partials[blockIdx.x] = s_rv[0];
    }
}

// ---------------- final deterministic loss reduction ------------------------
__global__ void loss_kernel(float* __restrict__ out, long long loss_off,
                            int nblocks, float inv_bnd) {
    __shared__ float s[256];
    int tid = threadIdx.x;
    float v = 0.f;
    for (int i = tid; i < nblocks; i += 256) v += g_partials[i];
    s[tid] = v;
    __syncthreads();
    for (int st = 128; st > 0; st >>= 1) {
        if (tid < st) s[tid] += s[tid + st];
        __syncthreads();
    }
    if (tid == 0) out[loss_off] = 0.25f * s[0] * inv_bnd;
}

// ---------------------------------------------------------------------------
extern "C" void kernel_launch(void* const* d_in, const int* in_sizes, int n_in,
                              void* d_out, int out_size) {
    const float* z    = (const float*)d_in[0];
    const void*  mask = d_in[1];
    const float* cb   = (const float*)d_in[2];
    float* out = (float*)d_out;

    long long BND = in_sizes[0];     // 16777216
    int T = in_sizes[1];             // 65536

    cudaFuncSetAttribute(vq_mma_kernel, cudaFuncAttributeMaxDynamicSharedMemorySize, SMEM_TOTAL);

    int mask_words = (T / 4 < 1024) ? (T / 4) : 1024;
    mask_kind_kernel<<<1, 256>>>(mask, mask_words);
    convert_cb_kernel<<<32, 512>>>(cb);

    int write_idx  = ((long long)out_size >= BND + T) ? 1 : 0;
    int write_loss = ((long long)out_size >= BND + T + 1) ? 1 : 0;

    vq_mma_kernel<<<NTILES, 256, SMEM_TOTAL>>>(z, mask, cb, out, T, write_idx, write_loss);

    if (write_loss)
        loss_kernel<<<1, 256>>>(out, BND + T, NTILES, 1.0f / (float)BND);
}